// round 15
// baseline (speedup 1.0000x reference)
#include <cuda_runtime.h>
#include <math.h>

#define NB 4
#define CIN 1024
#define CMID 512
#define NPIX 4096
#define MTOT (NB*NPIX)      /* 16384 */
#define KTOT 9216
#define NSPLIT 4
#define KQ (KTOT/NSPLIT)    /* 2304 */
#define NANCH 36864
#define PRE_TOPN 6000
#define POST_TOPN 300
#define SORT_N 8192
#define NBUCKET 65536
#define NEGF (-1.0e10f)
#define PSZ ((size_t)MTOT*CMID)

static __device__ float g_wt[KTOT*CMID];
static __device__ float g_part[(size_t)NSPLIT*MTOT*CMID];
static __device__ float g_boxes[NB*NANCH*4];
static __device__ unsigned g_sbits[NB*NANCH];
static __device__ int g_hist[NB*NBUCKET];
static __device__ int g_thr[NB];
static __device__ int g_cnt[NB];
static __device__ unsigned long long g_sel[NB*SORT_N];

__constant__ float c_wa[9] = {184.f,368.f,736.f,128.f,256.f,512.f, 88.f,176.f,352.f};
__constant__ float c_ha[9] = { 96.f,192.f,384.f,128.f,256.f,512.f,176.f,352.f,704.f};

// ---- packed f32x2 helpers ---------------------------------------------------
__device__ __forceinline__ unsigned long long pk2(float x, float y){
    unsigned long long r;
    asm("mov.b64 %0, {%1,%2};" : "=l"(r) : "f"(x), "f"(y));
    return r;
}
__device__ __forceinline__ void upk2(unsigned long long v, float& x, float& y){
    asm("mov.b64 {%0,%1}, %2;" : "=f"(x), "=f"(y) : "l"(v));
}
__device__ __forceinline__ void fma2(unsigned long long& d, unsigned long long a, unsigned long long b){
    asm("fma.rn.f32x2 %0, %1, %2, %0;" : "+l"(d) : "l"(a), "l"(b));
}

// ---------------------------------------------------------------------------
// Fused prep: blocks [0,512) transpose weights; blocks [512,1536) zero state.
// ---------------------------------------------------------------------------
__global__ void __launch_bounds__(256)
prep_kernel(const float* __restrict__ w){
    const int bid = blockIdx.x;
    const int tid = threadIdx.x;
    if (bid < 512){
        __shared__ float s[128][73];
        const int n0 = (bid >> 7) * 128;
        const int c0 = (bid & 127) * 8;
        const int n  = tid >> 1;
        const int half = tid & 1;
        const float* src = w + (size_t)(n0+n)*KTOT + c0*9 + half*36;
#pragma unroll
        for (int i=0;i<36;i++) s[n][half*36 + i] = src[i];
        __syncthreads();
        const int nn = tid & 127;
        const int u  = tid >> 7;
#pragma unroll
        for (int si=0; si<36; ++si){
            int slot = u*36 + si;
            int cc = slot / 9, r = slot - cc*9;
            g_wt[(size_t)(r*1024 + c0 + cc)*512 + n0 + nn] = s[nn][slot];
        }
    } else {
        int i = (bid - 512)*256 + tid;
        if (i < NB*NBUCKET) g_hist[i] = 0;
        if (i < NB*SORT_N)  g_sel[i] = 0ULL;
        if (i < NB)         g_cnt[i] = 0;
    }
}

// ---------------------------------------------------------------------------
// PROVEN fp32 split-K conv (R14, unchanged).
// ---------------------------------------------------------------------------
__global__ void __launch_bounds__(256,2)
conv3x3_kernel(const float* __restrict__ X){
    __shared__ __align__(16) float As[2][8][128];
    __shared__ __align__(16) float Bs[2][8][128];
    const int tid = threadIdx.x;
    const int n0 = blockIdx.x * 128;
    const int m0 = blockIdx.y * 128;
    const int kq = blockIdx.z;
    const int KT0 = kq * (KQ/8);

    const int a_m = tid & 127;
    const int a_k = (tid >> 7) << 2;
    const int am  = m0 + a_m;
    const int bb  = am >> 12;
    const int yx  = am & 4095;
    const int py  = yx >> 6;
    const int px  = yx & 63;
    const float* Xb = X + (size_t)bb * (CIN*NPIX);

    const int w_n = tid & 127;
    const int w_k = (tid >> 7) << 2;

    const int tm = (tid >> 4) << 2;
    const int tn = (tid & 15) << 2;

    unsigned long long acc2[8][4];
#pragma unroll
    for (int i=0;i<8;i++)
#pragma unroll
        for (int jh=0;jh<4;jh++) acc2[i][jh] = 0ULL;

    float ar[4], br[4];
    {
        const int kb = KT0 << 3;
        const int r  = kb >> 10;
        const int cb = kb & 1023;
        const int ky = r/3, kx = r - ky*3;
        const int oy = py + ky - 1, ox = px + kx - 1;
        const bool ok = ((unsigned)oy < 64u) && ((unsigned)ox < 64u);
        const float* ap = Xb + ((cb + a_k)*4096 + oy*64 + ox);
#pragma unroll
        for (int i=0;i<4;i++) ar[i] = ok ? ap[i*4096] : 0.f;
        const float* wp = g_wt + (size_t)(kb + w_k)*512 + n0 + w_n;
#pragma unroll
        for (int i=0;i<4;i++) br[i] = wp[i*512];
#pragma unroll
        for (int i=0;i<4;i++) As[0][a_k+i][a_m] = ar[i];
#pragma unroll
        for (int i=0;i<4;i++) Bs[0][w_k+i][w_n] = br[i];
    }
    __syncthreads();

    int buf = 0;
    const int NKT = KQ/8;
    for (int kt = 0; kt < NKT; ++kt) {
        if (kt + 1 < NKT) {
            const int kb = (KT0 + kt + 1) << 3;
            const int r  = kb >> 10;
            const int cb = kb & 1023;
            const int ky = r/3, kx = r - ky*3;
            const int oy = py + ky - 1, ox = px + kx - 1;
            const bool ok = ((unsigned)oy < 64u) && ((unsigned)ox < 64u);
            const float* ap = Xb + ((cb + a_k)*4096 + oy*64 + ox);
#pragma unroll
            for (int i=0;i<4;i++) ar[i] = ok ? ap[i*4096] : 0.f;
            const float* wp = g_wt + (size_t)(kb + w_k)*512 + n0 + w_n;
#pragma unroll
            for (int i=0;i<4;i++) br[i] = wp[i*512];
        }
#pragma unroll
        for (int kk=0;kk<8;kk++){
            float4 t0 = *(const float4*)&As[buf][kk][tm];
            float4 t1 = *(const float4*)&As[buf][kk][64+tm];
            const unsigned long long* Bp0 = (const unsigned long long*)&Bs[buf][kk][tn];
            const unsigned long long* Bp1 = (const unsigned long long*)&Bs[buf][kk][64+tn];
            unsigned long long bp[4];
            bp[0]=Bp0[0]; bp[1]=Bp0[1]; bp[2]=Bp1[0]; bp[3]=Bp1[1];
            unsigned long long ap2[8];
            ap2[0]=pk2(t0.x,t0.x); ap2[1]=pk2(t0.y,t0.y);
            ap2[2]=pk2(t0.z,t0.z); ap2[3]=pk2(t0.w,t0.w);
            ap2[4]=pk2(t1.x,t1.x); ap2[5]=pk2(t1.y,t1.y);
            ap2[6]=pk2(t1.z,t1.z); ap2[7]=pk2(t1.w,t1.w);
#pragma unroll
            for (int jh=0;jh<4;jh++)
#pragma unroll
                for (int i=0;i<8;i++)
                    fma2(acc2[i][jh], ap2[i], bp[jh]);
        }
        if (kt + 1 < NKT) {
            const int nb2 = buf^1;
#pragma unroll
            for (int i=0;i<4;i++) As[nb2][a_k+i][a_m] = ar[i];
#pragma unroll
            for (int i=0;i<4;i++) Bs[nb2][w_k+i][w_n] = br[i];
        }
        __syncthreads();
        buf ^= 1;
    }

    float* gp = g_part + (size_t)kq * PSZ;
#pragma unroll
    for (int i=0;i<8;i++){
        const int mr = m0 + ((i<4)? (tm+i) : (64+tm+i-4));
        float* op = gp + (size_t)mr*CMID + n0;
        float v0,v1,v2,v3,v4,v5,v6,v7;
        upk2(acc2[i][0], v0, v1);
        upk2(acc2[i][1], v2, v3);
        upk2(acc2[i][2], v4, v5);
        upk2(acc2[i][3], v6, v7);
        float4 q0, q1;
        q0.x=v0; q0.y=v1; q0.z=v2; q0.w=v3;
        q1.x=v4; q1.y=v5; q1.z=v6; q1.w=v7;
        *(float4*)(op + tn)      = q0;
        *(float4*)(op + 64 + tn) = q1;
    }
}

// ---------------------------------------------------------------------------
// Head with FUSED split-K combine: fr = relu(((p0+p1)+p2)+p3 + bias) inline
// (identical add order to the former combine kernel -> identical scores).
// ---------------------------------------------------------------------------
__global__ void __launch_bounds__(512)
head_kernel(const float* __restrict__ cls_w, const float* __restrict__ cls_b,
            const float* __restrict__ bbox_w, const float* __restrict__ bbox_b,
            const float* __restrict__ conv_b, const float* __restrict__ im_info){
    extern __shared__ float ws[];
    __shared__ float bs[54];
    __shared__ float bs2[512];
    __shared__ float obuf[16][4][54];
    const int tid = threadIdx.x;
    for (int i = tid; i < 18*512; i += 512) ws[i] = cls_w[i];
    for (int i = tid; i < 36*512; i += 512) ws[18*512 + i] = bbox_w[i];
    bs2[tid] = conv_b[tid];
    if (tid < 18) bs[tid] = cls_b[tid];
    else if (tid < 54) bs[tid] = bbox_b[tid-18];
    __syncthreads();

    const int lane = tid & 31;
    const int warp = tid >> 5;
    const int gw = blockIdx.x*16 + warp;
    const int nw = gridDim.x*16;
    for (int mb = gw*4; mb < MTOT; mb += nw*4) {
        float fr[4][16];
#pragma unroll
        for (int p=0;p<4;p++){
            const size_t rbase = (size_t)(mb+p)*CMID + lane;
#pragma unroll
            for (int j=0;j<16;j++){
                const size_t a = rbase + 32*j;
                float p0 = g_part[a];
                float p1 = g_part[PSZ + a];
                float p2 = g_part[2*PSZ + a];
                float p3 = g_part[3*PSZ + a];
                fr[p][j] = fmaxf(((p0 + p1) + p2) + p3 + bs2[lane + 32*j], 0.f);
            }
        }
        for (int t=0;t<54;t++){
            const float* wr = ws + t*512;
            float s0=0.f, s1=0.f, s2=0.f, s3=0.f;
#pragma unroll
            for (int j=0;j<16;j++){
                float wv = wr[lane+32*j];
                s0 += fr[0][j]*wv; s1 += fr[1][j]*wv;
                s2 += fr[2][j]*wv; s3 += fr[3][j]*wv;
            }
#pragma unroll
            for (int d=16; d>0; d>>=1){
                s0 += __shfl_xor_sync(0xffffffffu, s0, d);
                s1 += __shfl_xor_sync(0xffffffffu, s1, d);
                s2 += __shfl_xor_sync(0xffffffffu, s2, d);
                s3 += __shfl_xor_sync(0xffffffffu, s3, d);
            }
            if (lane==0){
                float bv = bs[t];
                obuf[warp][0][t] = s0 + bv;
                obuf[warp][1][t] = s1 + bv;
                obuf[warp][2][t] = s2 + bv;
                obuf[warp][3][t] = s3 + bv;
            }
        }
        __syncwarp();
#pragma unroll
        for (int p=0;p<4;p++){
            if (lane < 9) {
                const float* o = obuf[warp][p];
                const int m = mb + p;
                const int a  = lane;
                const int b  = m >> 12;
                const int yx = m & 4095;
                const int py = yx >> 6, px = yx & 63;
                float c0 = o[a], c1 = o[9+a];
                float mx = fmaxf(c0,c1);
                float e0 = expf(c0-mx), e1 = expf(c1-mx);
                float sc = e1/(e0+e1);
                float dx = o[18+a*4+0], dy = o[18+a*4+1];
                float dw = o[18+a*4+2], dh = o[18+a*4+3];
                float wa = c_wa[a], ha = c_ha[a];
                float cxa = 7.5f + 16.f*(float)px;
                float cya = 7.5f + 16.f*(float)py;
                float cx = dx*wa + cxa;
                float cy = dy*ha + cya;
                float pw = expf(dw)*wa;
                float ph = expf(dh)*ha;
                float imh = im_info[b*3+0], imw = im_info[b*3+1];
                float x1 = fminf(fmaxf(cx - 0.5f*pw, 0.f), imw - 1.f);
                float y1 = fminf(fmaxf(cy - 0.5f*ph, 0.f), imh - 1.f);
                float x2 = fminf(fmaxf(cx + 0.5f*pw, 0.f), imw - 1.f);
                float y2 = fminf(fmaxf(cy + 0.5f*ph, 0.f), imh - 1.f);
                const int idx = yx*9 + a;
                float* bp = g_boxes + ((size_t)b*NANCH + idx)*4;
                bp[0]=x1; bp[1]=y1; bp[2]=x2; bp[3]=y2;
                unsigned bits = __float_as_uint(sc);
                g_sbits[b*NANCH + idx] = bits;
                atomicAdd(&g_hist[b*NBUCKET + (bits>>16)], 1);
            }
        }
        __syncwarp();
    }
}

// ---------------------------------------------------------------------------
__global__ void __launch_bounds__(1024) thresh_kernel(){
    __shared__ int csum[1024];
    const int b = blockIdx.x;
    const int t = threadIdx.x;
    const int* h = g_hist + b*NBUCKET;
    const int base = t*64;
    int s = 0;
    for (int i=0;i<64;i++) s += h[base+i];
    csum[t] = s;
    __syncthreads();
    for (int d=1; d<1024; d<<=1){
        int add = (t+d < 1024) ? csum[t+d] : 0;
        __syncthreads();
        csum[t] += add;
        __syncthreads();
    }
    int St = csum[t];
    int Sn = (t+1 < 1024) ? csum[t+1] : 0;
    if (St >= PRE_TOPN && Sn < PRE_TOPN){
        int acc = Sn;
        int T = base;
        for (int i=63;i>=0;i--){
            acc += h[base+i];
            if (acc >= PRE_TOPN){ T = base+i; break; }
        }
        g_thr[b] = T;
    }
}

__global__ void compact_kernel(){
    int i = blockIdx.x*256 + threadIdx.x;
    if (i >= NB*NANCH) return;
    int b = i / NANCH;
    int idx = i - b*NANCH;
    unsigned bits = g_sbits[i];
    if ((int)(bits >> 16) >= g_thr[b]){
        int p = atomicAdd(&g_cnt[b], 1);
        if (p < SORT_N)
            g_sel[b*SORT_N + p] = ((unsigned long long)bits << 32) | (unsigned)(~idx);
    }
}

// ---------------------------------------------------------------------------
// FUSED sort (bitonic, 8192 keys, descending) + greedy NMS (register boxes).
// Keys stay in smem between phases: no gmem writeback/reload, one launch.
// ---------------------------------------------------------------------------
#define SN_SMEM (SORT_N*8 + PRE_TOPN*6*4)
__global__ void __launch_bounds__(1024) sortnms_kernel(float* __restrict__ out){
    extern __shared__ char smraw[];
    unsigned long long* sh = (unsigned long long*)smraw;          // 64 KB keys
    float* X1 = (float*)(smraw + SORT_N*8);                       // 144 KB boxes
    float* Y1 = X1 + PRE_TOPN;
    float* X2 = Y1 + PRE_TOPN;
    float* Y2 = X2 + PRE_TOPN;
    float* AR = Y2 + PRE_TOPN;
    float* SC = AR + PRE_TOPN;
    __shared__ int   s_wmin[32];
    __shared__ int   s_pick;
    __shared__ float s_box[5];
    const int tid = threadIdx.x;
    const int lane = tid & 31;
    const int warp = tid >> 5;
    const int b = blockIdx.x;

    // ---- phase 1: bitonic sort in smem ----
    const unsigned long long* gs = g_sel + b*SORT_N;
    for (int i=tid;i<SORT_N;i+=1024) sh[i] = gs[i];
    __syncthreads();
    for (int k=2;k<=SORT_N;k<<=1){
        for (int j=k>>1;j>0;j>>=1){
            for (int t=tid;t<SORT_N/2;t+=1024){
                int i  = 2*t - (t & (j-1));
                int ix = i + j;
                unsigned long long a = sh[i], c = sh[ix];
                bool dir = ((i & k) == 0);
                bool sw  = dir ? (a < c) : (a > c);
                if (sw){ sh[i]=c; sh[ix]=a; }
            }
            __syncthreads();
        }
    }

    // ---- phase 2: build box arrays from sorted keys ----
    for (int i=tid;i<PRE_TOPN;i+=1024){
        unsigned long long kv = sh[i];
        unsigned idx = ~(unsigned)(kv & 0xFFFFFFFFull);
        float sc = __uint_as_float((unsigned)(kv >> 32));
        const float* bp = g_boxes + ((size_t)b*NANCH + idx)*4;
        float x1=bp[0], y1=bp[1], x2=bp[2], y2=bp[3];
        X1[i]=x1; Y1[i]=y1; X2[i]=x2; Y2[i]=y2;
        AR[i]=(x2-x1+1.f)*(y2-y1+1.f);
        SC[i]=sc;
    }
    __syncthreads();

    // ---- phase 3: register-resident greedy NMS ----
    float mx1[6], my1[6], mx2[6], my2[6], mar[6];
    unsigned live = 0;
#pragma unroll
    for (int j=0;j<6;j++){
        int i = tid + j*1024;
        if (i < PRE_TOPN){
            mx1[j]=X1[i]; my1[j]=Y1[i]; mx2[j]=X2[i]; my2[j]=Y2[i]; mar[j]=AR[i];
            live |= (1u<<j);
        } else {
            mx1[j]=0.f; my1[j]=0.f; mx2[j]=0.f; my2[j]=0.f; mar[j]=1.f;
        }
    }

    for (int it=0; it<POST_TOPN; ++it){
        int lmin = 0x7FFFFFFF;
        if (live) lmin = tid + (__ffs(live)-1)*1024;
#pragma unroll
        for (int d=16; d>0; d>>=1) lmin = min(lmin, __shfl_xor_sync(0xffffffffu, lmin, d));
        if (lane == 0) s_wmin[warp] = lmin;
        __syncthreads();
        if (tid < 32){
            int v = s_wmin[lane];
#pragma unroll
            for (int d=16; d>0; d>>=1) v = min(v, __shfl_xor_sync(0xffffffffu, v, d));
            if (tid == 0){
                s_pick = v;
                float* r = out + (size_t)(b*POST_TOPN + it)*5;
                if (v < PRE_TOPN){
                    float x1=X1[v], y1=Y1[v], x2=X2[v], y2=Y2[v];
                    s_box[0]=x1; s_box[1]=y1; s_box[2]=x2; s_box[3]=y2; s_box[4]=AR[v];
                    r[0]=(float)b; r[1]=x1; r[2]=y1; r[3]=x2; r[4]=y2;
                    out[NB*POST_TOPN*5 + b*POST_TOPN + it] = SC[v];
                } else {
                    r[0]=0.f; r[1]=0.f; r[2]=0.f; r[3]=0.f; r[4]=0.f;
                    out[NB*POST_TOPN*5 + b*POST_TOPN + it] = 0.f;
                }
            }
        }
        __syncthreads();
        if (s_pick < PRE_TOPN && live){
            float bx1=s_box[0], by1=s_box[1], bx2=s_box[2], by2=s_box[3], ba=s_box[4];
#pragma unroll
            for (int j=0;j<6;j++){
                if (live & (1u<<j)){
                    float xx1 = fmaxf(bx1, mx1[j]);
                    float yy1 = fmaxf(by1, my1[j]);
                    float xx2 = fminf(bx2, mx2[j]);
                    float yy2 = fminf(by2, my2[j]);
                    float iw = fmaxf(xx2-xx1+1.f, 0.f);
                    float ih = fmaxf(yy2-yy1+1.f, 0.f);
                    float inter = iw*ih;
                    float iou = inter/(ba + mar[j] - inter);
                    if (iou > 0.7f) live &= ~(1u<<j);
                }
            }
        }
    }
}

// ---------------------------------------------------------------------------
extern "C" void kernel_launch(void* const* d_in, const int* in_sizes, int n_in,
                              void* d_out, int out_size) {
    (void)in_sizes; (void)n_in; (void)out_size;
    const float* base_feat = (const float*)d_in[0];
    const float* im_info   = (const float*)d_in[1];
    const float* conv_w    = (const float*)d_in[4];
    const float* conv_b    = (const float*)d_in[5];
    const float* cls_w     = (const float*)d_in[6];
    const float* cls_b     = (const float*)d_in[7];
    const float* bbox_w    = (const float*)d_in[8];
    const float* bbox_b    = (const float*)d_in[9];
    float* out = (float*)d_out;

    cudaFuncSetAttribute(head_kernel, cudaFuncAttributeMaxDynamicSharedMemorySize, 54*512*4);
    cudaFuncSetAttribute(sortnms_kernel, cudaFuncAttributeMaxDynamicSharedMemorySize, SN_SMEM);

    prep_kernel<<<1536, 256>>>(conv_w);
    conv3x3_kernel<<<dim3(4,128,NSPLIT), 256>>>(base_feat);
    head_kernel<<<148, 512, 54*512*4>>>(cls_w, cls_b, bbox_w, bbox_b, conv_b, im_info);
    thresh_kernel<<<NB, 1024>>>();
    compact_kernel<<<(NB*NANCH + 255)/256, 256>>>();
    sortnms_kernel<<<NB, 1024, SN_SMEM>>>(out);
}

// round 16
// speedup vs baseline: 1.0089x; 1.0089x over previous
#include <cuda_runtime.h>
#include <math.h>

#define NB 4
#define CIN 1024
#define CMID 512
#define NPIX 4096
#define MTOT (NB*NPIX)      /* 16384 */
#define KTOT 9216
#define NSPLIT 4
#define KQ (KTOT/NSPLIT)    /* 2304 */
#define NANCH 36864
#define PRE_TOPN 6000
#define POST_TOPN 300
#define SORT_N 8192
#define NBUCKET 65536
#define NEGF (-1.0e10f)
#define PSZ ((size_t)MTOT*CMID)

static __device__ float g_wt[KTOT*CMID];
static __device__ float g_part[(size_t)NSPLIT*MTOT*CMID];
static __device__ float g_feat[(size_t)MTOT*CMID];
static __device__ float g_boxes[NB*NANCH*4];
static __device__ unsigned g_sbits[NB*NANCH];
static __device__ int g_hist[NB*NBUCKET];
static __device__ int g_thr[NB];
static __device__ int g_cnt[NB];
static __device__ unsigned long long g_sel[NB*SORT_N];

__constant__ float c_wa[9] = {184.f,368.f,736.f,128.f,256.f,512.f, 88.f,176.f,352.f};
__constant__ float c_ha[9] = { 96.f,192.f,384.f,128.f,256.f,512.f,176.f,352.f,704.f};

// ---- packed f32x2 helpers ---------------------------------------------------
__device__ __forceinline__ unsigned long long pk2(float x, float y){
    unsigned long long r;
    asm("mov.b64 %0, {%1,%2};" : "=l"(r) : "f"(x), "f"(y));
    return r;
}
__device__ __forceinline__ void upk2(unsigned long long v, float& x, float& y){
    asm("mov.b64 {%0,%1}, %2;" : "=f"(x), "=f"(y) : "l"(v));
}
__device__ __forceinline__ void fma2(unsigned long long& d, unsigned long long a, unsigned long long b){
    asm("fma.rn.f32x2 %0, %1, %2, %0;" : "+l"(d) : "l"(a), "l"(b));
}

// ---------------------------------------------------------------------------
// Fused prep: blocks [0,512) transpose weights; blocks [512,1536) zero state.
// ---------------------------------------------------------------------------
__global__ void __launch_bounds__(256)
prep_kernel(const float* __restrict__ w){
    const int bid = blockIdx.x;
    const int tid = threadIdx.x;
    if (bid < 512){
        __shared__ float s[128][73];
        const int n0 = (bid >> 7) * 128;
        const int c0 = (bid & 127) * 8;
        const int n  = tid >> 1;
        const int half = tid & 1;
        const float* src = w + (size_t)(n0+n)*KTOT + c0*9 + half*36;
#pragma unroll
        for (int i=0;i<36;i++) s[n][half*36 + i] = src[i];
        __syncthreads();
        const int nn = tid & 127;
        const int u  = tid >> 7;
#pragma unroll
        for (int si=0; si<36; ++si){
            int slot = u*36 + si;
            int cc = slot / 9, r = slot - cc*9;
            g_wt[(size_t)(r*1024 + c0 + cc)*512 + n0 + nn] = s[nn][slot];
        }
    } else {
        int i = (bid - 512)*256 + tid;
        if (i < NB*NBUCKET) g_hist[i] = 0;
        if (i < NB*SORT_N)  g_sel[i] = 0ULL;
        if (i < NB)         g_cnt[i] = 0;
    }
}

// ---------------------------------------------------------------------------
// PROVEN fp32 split-K conv (R14, unchanged).
// ---------------------------------------------------------------------------
__global__ void __launch_bounds__(256,2)
conv3x3_kernel(const float* __restrict__ X){
    __shared__ __align__(16) float As[2][8][128];
    __shared__ __align__(16) float Bs[2][8][128];
    const int tid = threadIdx.x;
    const int n0 = blockIdx.x * 128;
    const int m0 = blockIdx.y * 128;
    const int kq = blockIdx.z;
    const int KT0 = kq * (KQ/8);

    const int a_m = tid & 127;
    const int a_k = (tid >> 7) << 2;
    const int am  = m0 + a_m;
    const int bb  = am >> 12;
    const int yx  = am & 4095;
    const int py  = yx >> 6;
    const int px  = yx & 63;
    const float* Xb = X + (size_t)bb * (CIN*NPIX);

    const int w_n = tid & 127;
    const int w_k = (tid >> 7) << 2;

    const int tm = (tid >> 4) << 2;
    const int tn = (tid & 15) << 2;

    unsigned long long acc2[8][4];
#pragma unroll
    for (int i=0;i<8;i++)
#pragma unroll
        for (int jh=0;jh<4;jh++) acc2[i][jh] = 0ULL;

    float ar[4], br[4];
    {
        const int kb = KT0 << 3;
        const int r  = kb >> 10;
        const int cb = kb & 1023;
        const int ky = r/3, kx = r - ky*3;
        const int oy = py + ky - 1, ox = px + kx - 1;
        const bool ok = ((unsigned)oy < 64u) && ((unsigned)ox < 64u);
        const float* ap = Xb + ((cb + a_k)*4096 + oy*64 + ox);
#pragma unroll
        for (int i=0;i<4;i++) ar[i] = ok ? ap[i*4096] : 0.f;
        const float* wp = g_wt + (size_t)(kb + w_k)*512 + n0 + w_n;
#pragma unroll
        for (int i=0;i<4;i++) br[i] = wp[i*512];
#pragma unroll
        for (int i=0;i<4;i++) As[0][a_k+i][a_m] = ar[i];
#pragma unroll
        for (int i=0;i<4;i++) Bs[0][w_k+i][w_n] = br[i];
    }
    __syncthreads();

    int buf = 0;
    const int NKT = KQ/8;
    for (int kt = 0; kt < NKT; ++kt) {
        if (kt + 1 < NKT) {
            const int kb = (KT0 + kt + 1) << 3;
            const int r  = kb >> 10;
            const int cb = kb & 1023;
            const int ky = r/3, kx = r - ky*3;
            const int oy = py + ky - 1, ox = px + kx - 1;
            const bool ok = ((unsigned)oy < 64u) && ((unsigned)ox < 64u);
            const float* ap = Xb + ((cb + a_k)*4096 + oy*64 + ox);
#pragma unroll
            for (int i=0;i<4;i++) ar[i] = ok ? ap[i*4096] : 0.f;
            const float* wp = g_wt + (size_t)(kb + w_k)*512 + n0 + w_n;
#pragma unroll
            for (int i=0;i<4;i++) br[i] = wp[i*512];
        }
#pragma unroll
        for (int kk=0;kk<8;kk++){
            float4 t0 = *(const float4*)&As[buf][kk][tm];
            float4 t1 = *(const float4*)&As[buf][kk][64+tm];
            const unsigned long long* Bp0 = (const unsigned long long*)&Bs[buf][kk][tn];
            const unsigned long long* Bp1 = (const unsigned long long*)&Bs[buf][kk][64+tn];
            unsigned long long bp[4];
            bp[0]=Bp0[0]; bp[1]=Bp0[1]; bp[2]=Bp1[0]; bp[3]=Bp1[1];
            unsigned long long ap2[8];
            ap2[0]=pk2(t0.x,t0.x); ap2[1]=pk2(t0.y,t0.y);
            ap2[2]=pk2(t0.z,t0.z); ap2[3]=pk2(t0.w,t0.w);
            ap2[4]=pk2(t1.x,t1.x); ap2[5]=pk2(t1.y,t1.y);
            ap2[6]=pk2(t1.z,t1.z); ap2[7]=pk2(t1.w,t1.w);
#pragma unroll
            for (int jh=0;jh<4;jh++)
#pragma unroll
                for (int i=0;i<8;i++)
                    fma2(acc2[i][jh], ap2[i], bp[jh]);
        }
        if (kt + 1 < NKT) {
            const int nb2 = buf^1;
#pragma unroll
            for (int i=0;i<4;i++) As[nb2][a_k+i][a_m] = ar[i];
#pragma unroll
            for (int i=0;i<4;i++) Bs[nb2][w_k+i][w_n] = br[i];
        }
        __syncthreads();
        buf ^= 1;
    }

    float* gp = g_part + (size_t)kq * PSZ;
#pragma unroll
    for (int i=0;i<8;i++){
        const int mr = m0 + ((i<4)? (tm+i) : (64+tm+i-4));
        float* op = gp + (size_t)mr*CMID + n0;
        float v0,v1,v2,v3,v4,v5,v6,v7;
        upk2(acc2[i][0], v0, v1);
        upk2(acc2[i][1], v2, v3);
        upk2(acc2[i][2], v4, v5);
        upk2(acc2[i][3], v6, v7);
        float4 q0, q1;
        q0.x=v0; q0.y=v1; q0.z=v2; q0.w=v3;
        q1.x=v4; q1.y=v5; q1.z=v6; q1.w=v7;
        *(float4*)(op + tn)      = q0;
        *(float4*)(op + 64 + tn) = q1;
    }
}

// ---------------------------------------------------------------------------
// Deterministic split-K combine: ((p0+p1)+p2)+p3 + bias, relu -> g_feat.
// ---------------------------------------------------------------------------
__global__ void __launch_bounds__(256)
combine_kernel(const float* __restrict__ bias){
    const size_t idx = ((size_t)blockIdx.x*256 + threadIdx.x) * 4;
    const int n = (int)(idx & (CMID-1));
    const float4 p0 = *(const float4*)(g_part + idx);
    const float4 p1 = *(const float4*)(g_part + PSZ + idx);
    const float4 p2 = *(const float4*)(g_part + 2*PSZ + idx);
    const float4 p3 = *(const float4*)(g_part + 3*PSZ + idx);
    const float4 bv = *(const float4*)(bias + n);
    float4 o;
    o.x = fmaxf(((p0.x + p1.x) + p2.x) + p3.x + bv.x, 0.f);
    o.y = fmaxf(((p0.y + p1.y) + p2.y) + p3.y + bv.y, 0.f);
    o.z = fmaxf(((p0.z + p1.z) + p2.z) + p3.z + bv.z, 0.f);
    o.w = fmaxf(((p0.w + p1.w) + p2.w) + p3.w + bv.w, 0.f);
    *(float4*)(g_feat + idx) = o;
}

// ---------------------------------------------------------------------------
// 1x1 heads + softmax + anchor decode + clip + histogram (R14 form).
// ---------------------------------------------------------------------------
__global__ void __launch_bounds__(512)
head_kernel(const float* __restrict__ cls_w, const float* __restrict__ cls_b,
            const float* __restrict__ bbox_w, const float* __restrict__ bbox_b,
            const float* __restrict__ im_info){
    extern __shared__ float ws[];
    __shared__ float bs[54];
    __shared__ float obuf[16][4][54];
    const int tid = threadIdx.x;
    for (int i = tid; i < 18*512; i += 512) ws[i] = cls_w[i];
    for (int i = tid; i < 36*512; i += 512) ws[18*512 + i] = bbox_w[i];
    if (tid < 18) bs[tid] = cls_b[tid];
    else if (tid < 54) bs[tid] = bbox_b[tid-18];
    __syncthreads();

    const int lane = tid & 31;
    const int warp = tid >> 5;
    const int gw = blockIdx.x*16 + warp;
    const int nw = gridDim.x*16;
    for (int mb = gw*4; mb < MTOT; mb += nw*4) {
        float fr[4][16];
#pragma unroll
        for (int p=0;p<4;p++){
            const float* f = g_feat + (size_t)(mb+p)*CMID;
#pragma unroll
            for (int j=0;j<16;j++) fr[p][j] = f[lane + 32*j];
        }
        for (int t=0;t<54;t++){
            const float* wr = ws + t*512;
            float s0=0.f, s1=0.f, s2=0.f, s3=0.f;
#pragma unroll
            for (int j=0;j<16;j++){
                float wv = wr[lane+32*j];
                s0 += fr[0][j]*wv; s1 += fr[1][j]*wv;
                s2 += fr[2][j]*wv; s3 += fr[3][j]*wv;
            }
#pragma unroll
            for (int d=16; d>0; d>>=1){
                s0 += __shfl_xor_sync(0xffffffffu, s0, d);
                s1 += __shfl_xor_sync(0xffffffffu, s1, d);
                s2 += __shfl_xor_sync(0xffffffffu, s2, d);
                s3 += __shfl_xor_sync(0xffffffffu, s3, d);
            }
            if (lane==0){
                float bv = bs[t];
                obuf[warp][0][t] = s0 + bv;
                obuf[warp][1][t] = s1 + bv;
                obuf[warp][2][t] = s2 + bv;
                obuf[warp][3][t] = s3 + bv;
            }
        }
        __syncwarp();
#pragma unroll
        for (int p=0;p<4;p++){
            if (lane < 9) {
                const float* o = obuf[warp][p];
                const int m = mb + p;
                const int a  = lane;
                const int b  = m >> 12;
                const int yx = m & 4095;
                const int py = yx >> 6, px = yx & 63;
                float c0 = o[a], c1 = o[9+a];
                float mx = fmaxf(c0,c1);
                float e0 = expf(c0-mx), e1 = expf(c1-mx);
                float sc = e1/(e0+e1);
                float dx = o[18+a*4+0], dy = o[18+a*4+1];
                float dw = o[18+a*4+2], dh = o[18+a*4+3];
                float wa = c_wa[a], ha = c_ha[a];
                float cxa = 7.5f + 16.f*(float)px;
                float cya = 7.5f + 16.f*(float)py;
                float cx = dx*wa + cxa;
                float cy = dy*ha + cya;
                float pw = expf(dw)*wa;
                float ph = expf(dh)*ha;
                float imh = im_info[b*3+0], imw = im_info[b*3+1];
                float x1 = fminf(fmaxf(cx - 0.5f*pw, 0.f), imw - 1.f);
                float y1 = fminf(fmaxf(cy - 0.5f*ph, 0.f), imh - 1.f);
                float x2 = fminf(fmaxf(cx + 0.5f*pw, 0.f), imw - 1.f);
                float y2 = fminf(fmaxf(cy + 0.5f*ph, 0.f), imh - 1.f);
                const int idx = yx*9 + a;
                float* bp = g_boxes + ((size_t)b*NANCH + idx)*4;
                bp[0]=x1; bp[1]=y1; bp[2]=x2; bp[3]=y2;
                unsigned bits = __float_as_uint(sc);
                g_sbits[b*NANCH + idx] = bits;
                atomicAdd(&g_hist[b*NBUCKET + (bits>>16)], 1);
            }
        }
        __syncwarp();
    }
}

// ---------------------------------------------------------------------------
// Threshold: int4 hist loads (16x LDG.128 per thread, MLP exposed).
// ---------------------------------------------------------------------------
__global__ void __launch_bounds__(1024) thresh_kernel(){
    __shared__ int csum[1024];
    const int b = blockIdx.x;
    const int t = threadIdx.x;
    const int4* h4 = (const int4*)(g_hist + b*NBUCKET);
    const int base4 = t*16;                 // 16 int4 = 64 buckets
    int s = 0;
    int lv[16];
#pragma unroll
    for (int i=0;i<16;i++){
        int4 v = h4[base4 + i];
        lv[i] = v.x + v.y + v.z + v.w;
    }
#pragma unroll
    for (int i=0;i<16;i++) s += lv[i];
    csum[t] = s;
    __syncthreads();
    for (int d=1; d<1024; d<<=1){
        int add = (t+d < 1024) ? csum[t+d] : 0;
        __syncthreads();
        csum[t] += add;
        __syncthreads();
    }
    int St = csum[t];
    int Sn = (t+1 < 1024) ? csum[t+1] : 0;
    if (St >= PRE_TOPN && Sn < PRE_TOPN){
        const int* h = g_hist + b*NBUCKET;
        const int base = t*64;
        int acc = Sn;
        int T = base;
        for (int i=63;i>=0;i--){
            acc += h[base+i];
            if (acc >= PRE_TOPN){ T = base+i; break; }
        }
        g_thr[b] = T;
    }
}

__global__ void compact_kernel(){
    int i = blockIdx.x*256 + threadIdx.x;
    if (i >= NB*NANCH) return;
    int b = i / NANCH;
    int idx = i - b*NANCH;
    unsigned bits = g_sbits[i];
    if ((int)(bits >> 16) >= g_thr[b]){
        int p = atomicAdd(&g_cnt[b], 1);
        if (p < SORT_N)
            g_sel[b*SORT_N + p] = ((unsigned long long)bits << 32) | (unsigned)(~idx);
    }
}

// ---------------------------------------------------------------------------
// FUSED sort (bitonic, 8192 keys, descending) + greedy NMS (register boxes).
// ---------------------------------------------------------------------------
#define SN_SMEM (SORT_N*8 + PRE_TOPN*6*4)
__global__ void __launch_bounds__(1024) sortnms_kernel(float* __restrict__ out){
    extern __shared__ char smraw[];
    unsigned long long* sh = (unsigned long long*)smraw;
    float* X1 = (float*)(smraw + SORT_N*8);
    float* Y1 = X1 + PRE_TOPN;
    float* X2 = Y1 + PRE_TOPN;
    float* Y2 = X2 + PRE_TOPN;
    float* AR = Y2 + PRE_TOPN;
    float* SC = AR + PRE_TOPN;
    __shared__ int   s_wmin[32];
    __shared__ int   s_pick;
    __shared__ float s_box[5];
    const int tid = threadIdx.x;
    const int lane = tid & 31;
    const int warp = tid >> 5;
    const int b = blockIdx.x;

    const unsigned long long* gs = g_sel + b*SORT_N;
    for (int i=tid;i<SORT_N;i+=1024) sh[i] = gs[i];
    __syncthreads();
    for (int k=2;k<=SORT_N;k<<=1){
        for (int j=k>>1;j>0;j>>=1){
            for (int t=tid;t<SORT_N/2;t+=1024){
                int i  = 2*t - (t & (j-1));
                int ix = i + j;
                unsigned long long a = sh[i], c = sh[ix];
                bool dir = ((i & k) == 0);
                bool sw  = dir ? (a < c) : (a > c);
                if (sw){ sh[i]=c; sh[ix]=a; }
            }
            __syncthreads();
        }
    }

    for (int i=tid;i<PRE_TOPN;i+=1024){
        unsigned long long kv = sh[i];
        unsigned idx = ~(unsigned)(kv & 0xFFFFFFFFull);
        float sc = __uint_as_float((unsigned)(kv >> 32));
        const float* bp = g_boxes + ((size_t)b*NANCH + idx)*4;
        float x1=bp[0], y1=bp[1], x2=bp[2], y2=bp[3];
        X1[i]=x1; Y1[i]=y1; X2[i]=x2; Y2[i]=y2;
        AR[i]=(x2-x1+1.f)*(y2-y1+1.f);
        SC[i]=sc;
    }
    __syncthreads();

    float mx1[6], my1[6], mx2[6], my2[6], mar[6];
    unsigned live = 0;
#pragma unroll
    for (int j=0;j<6;j++){
        int i = tid + j*1024;
        if (i < PRE_TOPN){
            mx1[j]=X1[i]; my1[j]=Y1[i]; mx2[j]=X2[i]; my2[j]=Y2[i]; mar[j]=AR[i];
            live |= (1u<<j);
        } else {
            mx1[j]=0.f; my1[j]=0.f; mx2[j]=0.f; my2[j]=0.f; mar[j]=1.f;
        }
    }

    for (int it=0; it<POST_TOPN; ++it){
        int lmin = 0x7FFFFFFF;
        if (live) lmin = tid + (__ffs(live)-1)*1024;
#pragma unroll
        for (int d=16; d>0; d>>=1) lmin = min(lmin, __shfl_xor_sync(0xffffffffu, lmin, d));
        if (lane == 0) s_wmin[warp] = lmin;
        __syncthreads();
        if (tid < 32){
            int v = s_wmin[lane];
#pragma unroll
            for (int d=16; d>0; d>>=1) v = min(v, __shfl_xor_sync(0xffffffffu, v, d));
            if (tid == 0){
                s_pick = v;
                float* r = out + (size_t)(b*POST_TOPN + it)*5;
                if (v < PRE_TOPN){
                    float x1=X1[v], y1=Y1[v], x2=X2[v], y2=Y2[v];
                    s_box[0]=x1; s_box[1]=y1; s_box[2]=x2; s_box[3]=y2; s_box[4]=AR[v];
                    r[0]=(float)b; r[1]=x1; r[2]=y1; r[3]=x2; r[4]=y2;
                    out[NB*POST_TOPN*5 + b*POST_TOPN + it] = SC[v];
                } else {
                    r[0]=0.f; r[1]=0.f; r[2]=0.f; r[3]=0.f; r[4]=0.f;
                    out[NB*POST_TOPN*5 + b*POST_TOPN + it] = 0.f;
                }
            }
        }
        __syncthreads();
        if (s_pick < PRE_TOPN && live){
            float bx1=s_box[0], by1=s_box[1], bx2=s_box[2], by2=s_box[3], ba=s_box[4];
#pragma unroll
            for (int j=0;j<6;j++){
                if (live & (1u<<j)){
                    float xx1 = fmaxf(bx1, mx1[j]);
                    float yy1 = fmaxf(by1, my1[j]);
                    float xx2 = fminf(bx2, mx2[j]);
                    float yy2 = fminf(by2, my2[j]);
                    float iw = fmaxf(xx2-xx1+1.f, 0.f);
                    float ih = fmaxf(yy2-yy1+1.f, 0.f);
                    float inter = iw*ih;
                    float iou = inter/(ba + mar[j] - inter);
                    if (iou > 0.7f) live &= ~(1u<<j);
                }
            }
        }
    }
}

// ---------------------------------------------------------------------------
extern "C" void kernel_launch(void* const* d_in, const int* in_sizes, int n_in,
                              void* d_out, int out_size) {
    (void)in_sizes; (void)n_in; (void)out_size;
    const float* base_feat = (const float*)d_in[0];
    const float* im_info   = (const float*)d_in[1];
    const float* conv_w    = (const float*)d_in[4];
    const float* conv_b    = (const float*)d_in[5];
    const float* cls_w     = (const float*)d_in[6];
    const float* cls_b     = (const float*)d_in[7];
    const float* bbox_w    = (const float*)d_in[8];
    const float* bbox_b    = (const float*)d_in[9];
    float* out = (float*)d_out;

    cudaFuncSetAttribute(head_kernel, cudaFuncAttributeMaxDynamicSharedMemorySize, 54*512*4);
    cudaFuncSetAttribute(sortnms_kernel, cudaFuncAttributeMaxDynamicSharedMemorySize, SN_SMEM);

    prep_kernel<<<1536, 256>>>(conv_w);
    conv3x3_kernel<<<dim3(4,128,NSPLIT), 256>>>(base_feat);
    combine_kernel<<<(MTOT*CMID/4 + 255)/256, 256>>>(conv_b);
    head_kernel<<<148, 512, 54*512*4>>>(cls_w, cls_b, bbox_w, bbox_b, im_info);
    thresh_kernel<<<NB, 1024>>>();
    compact_kernel<<<(NB*NANCH + 255)/256, 256>>>();
    sortnms_kernel<<<NB, 1024, SN_SMEM>>>(out);
}

// round 17
// speedup vs baseline: 1.0197x; 1.0107x over previous
#include <cuda_runtime.h>
#include <math.h>

#define NB 4
#define CIN 1024
#define CMID 512
#define NPIX 4096
#define MTOT (NB*NPIX)      /* 16384 */
#define KTOT 9216
#define NSPLIT 4
#define KQ (KTOT/NSPLIT)    /* 2304 */
#define NANCH 36864
#define PRE_TOPN 6000
#define POST_TOPN 300
#define SORT_N 8192
#define NBUCKET 65536
#define NEGF (-1.0e10f)

static __device__ float g_wt[KTOT*CMID];
static __device__ float g_part[(size_t)NSPLIT*MTOT*CMID];
static __device__ float g_feat[(size_t)MTOT*CMID];
static __device__ float g_boxes[NB*NANCH*4];
static __device__ unsigned g_sbits[NB*NANCH];
static __device__ int g_hist[NB*NBUCKET];
static __device__ int g_thr[NB];
static __device__ int g_cnt[NB];
static __device__ unsigned long long g_sel[NB*SORT_N];

__constant__ float c_wa[9] = {184.f,368.f,736.f,128.f,256.f,512.f, 88.f,176.f,352.f};
__constant__ float c_ha[9] = { 96.f,192.f,384.f,128.f,256.f,512.f,176.f,352.f,704.f};

// ---- packed f32x2 helpers ---------------------------------------------------
__device__ __forceinline__ unsigned long long pk2(float x, float y){
    unsigned long long r;
    asm("mov.b64 %0, {%1,%2};" : "=l"(r) : "f"(x), "f"(y));
    return r;
}
__device__ __forceinline__ void upk2(unsigned long long v, float& x, float& y){
    asm("mov.b64 {%0,%1}, %2;" : "=f"(x), "=f"(y) : "l"(v));
}
__device__ __forceinline__ void fma2(unsigned long long& d, unsigned long long a, unsigned long long b){
    asm("fma.rn.f32x2 %0, %1, %2, %0;" : "+l"(d) : "l"(a), "l"(b));
}

// ---------------------------------------------------------------------------
__global__ void __launch_bounds__(256)
transpose_w_kernel(const float* __restrict__ w){
    __shared__ float s[128][73];
    const int tid = threadIdx.x;
    const int n0 = blockIdx.y * 128;
    const int c0 = blockIdx.x * 8;
    const int n  = tid >> 1;
    const int half = tid & 1;
    const float* src = w + (size_t)(n0+n)*KTOT + c0*9 + half*36;
#pragma unroll
    for (int i=0;i<36;i++) s[n][half*36 + i] = src[i];
    __syncthreads();
    const int nn = tid & 127;
    const int u  = tid >> 7;
#pragma unroll
    for (int si=0; si<36; ++si){
        int slot = u*36 + si;
        int cc = slot / 9, r = slot - cc*9;
        g_wt[(size_t)(r*1024 + c0 + cc)*512 + n0 + nn] = s[nn][slot];
    }
}

__global__ void init_kernel(){
    int i = blockIdx.x*256 + threadIdx.x;
    if (i < NB*NBUCKET) g_hist[i] = 0;
    if (i < NB*SORT_N)  g_sel[i] = 0ULL;
    if (i < NB)         g_cnt[i] = 0;
}

// ---------------------------------------------------------------------------
// PROVEN fp32 split-K conv (R14, unchanged).
// ---------------------------------------------------------------------------
__global__ void __launch_bounds__(256,2)
conv3x3_kernel(const float* __restrict__ X){
    __shared__ __align__(16) float As[2][8][128];
    __shared__ __align__(16) float Bs[2][8][128];
    const int tid = threadIdx.x;
    const int n0 = blockIdx.x * 128;
    const int m0 = blockIdx.y * 128;
    const int kq = blockIdx.z;
    const int KT0 = kq * (KQ/8);

    const int a_m = tid & 127;
    const int a_k = (tid >> 7) << 2;
    const int am  = m0 + a_m;
    const int bb  = am >> 12;
    const int yx  = am & 4095;
    const int py  = yx >> 6;
    const int px  = yx & 63;
    const float* Xb = X + (size_t)bb * (CIN*NPIX);

    const int w_n = tid & 127;
    const int w_k = (tid >> 7) << 2;

    const int tm = (tid >> 4) << 2;
    const int tn = (tid & 15) << 2;

    unsigned long long acc2[8][4];
#pragma unroll
    for (int i=0;i<8;i++)
#pragma unroll
        for (int jh=0;jh<4;jh++) acc2[i][jh] = 0ULL;

    float ar[4], br[4];
    {
        const int kb = KT0 << 3;
        const int r  = kb >> 10;
        const int cb = kb & 1023;
        const int ky = r/3, kx = r - ky*3;
        const int oy = py + ky - 1, ox = px + kx - 1;
        const bool ok = ((unsigned)oy < 64u) && ((unsigned)ox < 64u);
        const float* ap = Xb + ((cb + a_k)*4096 + oy*64 + ox);
#pragma unroll
        for (int i=0;i<4;i++) ar[i] = ok ? ap[i*4096] : 0.f;
        const float* wp = g_wt + (size_t)(kb + w_k)*512 + n0 + w_n;
#pragma unroll
        for (int i=0;i<4;i++) br[i] = wp[i*512];
#pragma unroll
        for (int i=0;i<4;i++) As[0][a_k+i][a_m] = ar[i];
#pragma unroll
        for (int i=0;i<4;i++) Bs[0][w_k+i][w_n] = br[i];
    }
    __syncthreads();

    int buf = 0;
    const int NKT = KQ/8;
    for (int kt = 0; kt < NKT; ++kt) {
        if (kt + 1 < NKT) {
            const int kb = (KT0 + kt + 1) << 3;
            const int r  = kb >> 10;
            const int cb = kb & 1023;
            const int ky = r/3, kx = r - ky*3;
            const int oy = py + ky - 1, ox = px + kx - 1;
            const bool ok = ((unsigned)oy < 64u) && ((unsigned)ox < 64u);
            const float* ap = Xb + ((cb + a_k)*4096 + oy*64 + ox);
#pragma unroll
            for (int i=0;i<4;i++) ar[i] = ok ? ap[i*4096] : 0.f;
            const float* wp = g_wt + (size_t)(kb + w_k)*512 + n0 + w_n;
#pragma unroll
            for (int i=0;i<4;i++) br[i] = wp[i*512];
        }
#pragma unroll
        for (int kk=0;kk<8;kk++){
            float4 t0 = *(const float4*)&As[buf][kk][tm];
            float4 t1 = *(const float4*)&As[buf][kk][64+tm];
            const unsigned long long* Bp0 = (const unsigned long long*)&Bs[buf][kk][tn];
            const unsigned long long* Bp1 = (const unsigned long long*)&Bs[buf][kk][64+tn];
            unsigned long long bp[4];
            bp[0]=Bp0[0]; bp[1]=Bp0[1]; bp[2]=Bp1[0]; bp[3]=Bp1[1];
            unsigned long long ap2[8];
            ap2[0]=pk2(t0.x,t0.x); ap2[1]=pk2(t0.y,t0.y);
            ap2[2]=pk2(t0.z,t0.z); ap2[3]=pk2(t0.w,t0.w);
            ap2[4]=pk2(t1.x,t1.x); ap2[5]=pk2(t1.y,t1.y);
            ap2[6]=pk2(t1.z,t1.z); ap2[7]=pk2(t1.w,t1.w);
#pragma unroll
            for (int jh=0;jh<4;jh++)
#pragma unroll
                for (int i=0;i<8;i++)
                    fma2(acc2[i][jh], ap2[i], bp[jh]);
        }
        if (kt + 1 < NKT) {
            const int nb2 = buf^1;
#pragma unroll
            for (int i=0;i<4;i++) As[nb2][a_k+i][a_m] = ar[i];
#pragma unroll
            for (int i=0;i<4;i++) Bs[nb2][w_k+i][w_n] = br[i];
        }
        __syncthreads();
        buf ^= 1;
    }

    float* gp = g_part + (size_t)kq * MTOT * CMID;
#pragma unroll
    for (int i=0;i<8;i++){
        const int mr = m0 + ((i<4)? (tm+i) : (64+tm+i-4));
        float* op = gp + (size_t)mr*CMID + n0;
        float v0,v1,v2,v3,v4,v5,v6,v7;
        upk2(acc2[i][0], v0, v1);
        upk2(acc2[i][1], v2, v3);
        upk2(acc2[i][2], v4, v5);
        upk2(acc2[i][3], v6, v7);
        float4 q0, q1;
        q0.x=v0; q0.y=v1; q0.z=v2; q0.w=v3;
        q1.x=v4; q1.y=v5; q1.z=v6; q1.w=v7;
        *(float4*)(op + tn)      = q0;
        *(float4*)(op + 64 + tn) = q1;
    }
}

__global__ void __launch_bounds__(256)
combine_kernel(const float* __restrict__ bias){
    const size_t idx = ((size_t)blockIdx.x*256 + threadIdx.x) * 4;
    const int n = (int)(idx & (CMID-1));
    const float4 p0 = *(const float4*)(g_part + idx);
    const float4 p1 = *(const float4*)(g_part + (size_t)MTOT*CMID + idx);
    const float4 p2 = *(const float4*)(g_part + 2*(size_t)MTOT*CMID + idx);
    const float4 p3 = *(const float4*)(g_part + 3*(size_t)MTOT*CMID + idx);
    const float4 bv = *(const float4*)(bias + n);
    float4 o;
    o.x = fmaxf(((p0.x + p1.x) + p2.x) + p3.x + bv.x, 0.f);
    o.y = fmaxf(((p0.y + p1.y) + p2.y) + p3.y + bv.y, 0.f);
    o.z = fmaxf(((p0.z + p1.z) + p2.z) + p3.z + bv.z, 0.f);
    o.w = fmaxf(((p0.w + p1.w) + p2.w) + p3.w + bv.w, 0.f);
    *(float4*)(g_feat + idx) = o;
}

// ---------------------------------------------------------------------------
__global__ void __launch_bounds__(512)
head_kernel(const float* __restrict__ cls_w, const float* __restrict__ cls_b,
            const float* __restrict__ bbox_w, const float* __restrict__ bbox_b,
            const float* __restrict__ im_info){
    extern __shared__ float ws[];
    __shared__ float bs[54];
    __shared__ float obuf[16][4][54];
    const int tid = threadIdx.x;
    for (int i = tid; i < 18*512; i += 512) ws[i] = cls_w[i];
    for (int i = tid; i < 36*512; i += 512) ws[18*512 + i] = bbox_w[i];
    if (tid < 18) bs[tid] = cls_b[tid];
    else if (tid < 54) bs[tid] = bbox_b[tid-18];
    __syncthreads();

    const int lane = tid & 31;
    const int warp = tid >> 5;
    const int gw = blockIdx.x*16 + warp;
    const int nw = gridDim.x*16;
    for (int mb = gw*4; mb < MTOT; mb += nw*4) {
        float fr[4][16];
#pragma unroll
        for (int p=0;p<4;p++){
            const float* f = g_feat + (size_t)(mb+p)*CMID;
#pragma unroll
            for (int j=0;j<16;j++) fr[p][j] = f[lane + 32*j];
        }
        for (int t=0;t<54;t++){
            const float* wr = ws + t*512;
            float s0=0.f, s1=0.f, s2=0.f, s3=0.f;
#pragma unroll
            for (int j=0;j<16;j++){
                float wv = wr[lane+32*j];
                s0 += fr[0][j]*wv; s1 += fr[1][j]*wv;
                s2 += fr[2][j]*wv; s3 += fr[3][j]*wv;
            }
#pragma unroll
            for (int d=16; d>0; d>>=1){
                s0 += __shfl_xor_sync(0xffffffffu, s0, d);
                s1 += __shfl_xor_sync(0xffffffffu, s1, d);
                s2 += __shfl_xor_sync(0xffffffffu, s2, d);
                s3 += __shfl_xor_sync(0xffffffffu, s3, d);
            }
            if (lane==0){
                float bv = bs[t];
                obuf[warp][0][t] = s0 + bv;
                obuf[warp][1][t] = s1 + bv;
                obuf[warp][2][t] = s2 + bv;
                obuf[warp][3][t] = s3 + bv;
            }
        }
        __syncwarp();
#pragma unroll
        for (int p=0;p<4;p++){
            if (lane < 9) {
                const float* o = obuf[warp][p];
                const int m = mb + p;
                const int a  = lane;
                const int b  = m >> 12;
                const int yx = m & 4095;
                const int py = yx >> 6, px = yx & 63;
                float c0 = o[a], c1 = o[9+a];
                float mx = fmaxf(c0,c1);
                float e0 = expf(c0-mx), e1 = expf(c1-mx);
                float sc = e1/(e0+e1);
                float dx = o[18+a*4+0], dy = o[18+a*4+1];
                float dw = o[18+a*4+2], dh = o[18+a*4+3];
                float wa = c_wa[a], ha = c_ha[a];
                float cxa = 7.5f + 16.f*(float)px;
                float cya = 7.5f + 16.f*(float)py;
                float cx = dx*wa + cxa;
                float cy = dy*ha + cya;
                float pw = expf(dw)*wa;
                float ph = expf(dh)*ha;
                float imh = im_info[b*3+0], imw = im_info[b*3+1];
                float x1 = fminf(fmaxf(cx - 0.5f*pw, 0.f), imw - 1.f);
                float y1 = fminf(fmaxf(cy - 0.5f*ph, 0.f), imh - 1.f);
                float x2 = fminf(fmaxf(cx + 0.5f*pw, 0.f), imw - 1.f);
                float y2 = fminf(fmaxf(cy + 0.5f*ph, 0.f), imh - 1.f);
                const int idx = yx*9 + a;
                float* bp = g_boxes + ((size_t)b*NANCH + idx)*4;
                bp[0]=x1; bp[1]=y1; bp[2]=x2; bp[3]=y2;
                unsigned bits = __float_as_uint(sc);
                g_sbits[b*NANCH + idx] = bits;
                atomicAdd(&g_hist[b*NBUCKET + (bits>>16)], 1);
            }
        }
        __syncwarp();
    }
}

// ---------------------------------------------------------------------------
// Threshold: int4 hist loads (16x LDG.128 per thread, MLP exposed).
// ---------------------------------------------------------------------------
__global__ void __launch_bounds__(1024) thresh_kernel(){
    __shared__ int csum[1024];
    const int b = blockIdx.x;
    const int t = threadIdx.x;
    const int4* h4 = (const int4*)(g_hist + b*NBUCKET);
    const int base4 = t*16;
    int s = 0;
    int lv[16];
#pragma unroll
    for (int i=0;i<16;i++){
        int4 v = h4[base4 + i];
        lv[i] = v.x + v.y + v.z + v.w;
    }
#pragma unroll
    for (int i=0;i<16;i++) s += lv[i];
    csum[t] = s;
    __syncthreads();
    for (int d=1; d<1024; d<<=1){
        int add = (t+d < 1024) ? csum[t+d] : 0;
        __syncthreads();
        csum[t] += add;
        __syncthreads();
    }
    int St = csum[t];
    int Sn = (t+1 < 1024) ? csum[t+1] : 0;
    if (St >= PRE_TOPN && Sn < PRE_TOPN){
        const int* h = g_hist + b*NBUCKET;
        const int base = t*64;
        int acc = Sn;
        int T = base;
        for (int i=63;i>=0;i--){
            acc += h[base+i];
            if (acc >= PRE_TOPN){ T = base+i; break; }
        }
        g_thr[b] = T;
    }
}

__global__ void compact_kernel(){
    int i = blockIdx.x*256 + threadIdx.x;
    if (i >= NB*NANCH) return;
    int b = i / NANCH;
    int idx = i - b*NANCH;
    unsigned bits = g_sbits[i];
    if ((int)(bits >> 16) >= g_thr[b]){
        int p = atomicAdd(&g_cnt[b], 1);
        if (p < SORT_N)
            g_sel[b*SORT_N + p] = ((unsigned long long)bits << 32) | (unsigned)(~idx);
    }
}

__global__ void __launch_bounds__(1024) sort_kernel(){
    extern __shared__ unsigned long long sh[];
    const int b = blockIdx.x;
    unsigned long long* gs = g_sel + b*SORT_N;
    for (int i=threadIdx.x;i<SORT_N;i+=1024) sh[i] = gs[i];
    __syncthreads();
    for (int k=2;k<=SORT_N;k<<=1){
        for (int j=k>>1;j>0;j>>=1){
            for (int t=threadIdx.x;t<SORT_N/2;t+=1024){
                int i  = 2*t - (t & (j-1));
                int ix = i + j;
                unsigned long long a = sh[i], c = sh[ix];
                bool dir = ((i & k) == 0);
                bool sw  = dir ? (a < c) : (a > c);
                if (sw){ sh[i]=c; sh[ix]=a; }
            }
            __syncthreads();
        }
    }
    for (int i=threadIdx.x;i<SORT_N;i+=1024) gs[i]=sh[i];
}

// ---------------------------------------------------------------------------
// Greedy NMS: register-resident boxes + livemask (R14 version).
// ---------------------------------------------------------------------------
__global__ void __launch_bounds__(1024) nms_kernel(float* __restrict__ out){
    extern __shared__ float sm[];
    float* X1 = sm;
    float* Y1 = X1 + PRE_TOPN;
    float* X2 = Y1 + PRE_TOPN;
    float* Y2 = X2 + PRE_TOPN;
    float* AR = Y2 + PRE_TOPN;
    float* SC = AR + PRE_TOPN;
    __shared__ int   s_wmin[32];
    __shared__ int   s_pick;
    __shared__ float s_box[5];
    const int tid = threadIdx.x;
    const int lane = tid & 31;
    const int warp = tid >> 5;
    const int b = blockIdx.x;
    const unsigned long long* keys = g_sel + b*SORT_N;
    for (int i=tid;i<PRE_TOPN;i+=1024){
        unsigned long long kv = keys[i];
        unsigned idx = ~(unsigned)(kv & 0xFFFFFFFFull);
        float sc = __uint_as_float((unsigned)(kv >> 32));
        const float* bp = g_boxes + ((size_t)b*NANCH + idx)*4;
        float x1=bp[0], y1=bp[1], x2=bp[2], y2=bp[3];
        X1[i]=x1; Y1[i]=y1; X2[i]=x2; Y2[i]=y2;
        AR[i]=(x2-x1+1.f)*(y2-y1+1.f);
        SC[i]=sc;
    }
    __syncthreads();

    float mx1[6], my1[6], mx2[6], my2[6], mar[6];
    unsigned live = 0;
#pragma unroll
    for (int j=0;j<6;j++){
        int i = tid + j*1024;
        if (i < PRE_TOPN){
            mx1[j]=X1[i]; my1[j]=Y1[i]; mx2[j]=X2[i]; my2[j]=Y2[i]; mar[j]=AR[i];
            live |= (1u<<j);
        } else {
            mx1[j]=0.f; my1[j]=0.f; mx2[j]=0.f; my2[j]=0.f; mar[j]=1.f;
        }
    }

    for (int it=0; it<POST_TOPN; ++it){
        int lmin = 0x7FFFFFFF;
        if (live) lmin = tid + (__ffs(live)-1)*1024;
#pragma unroll
        for (int d=16; d>0; d>>=1) lmin = min(lmin, __shfl_xor_sync(0xffffffffu, lmin, d));
        if (lane == 0) s_wmin[warp] = lmin;
        __syncthreads();
        if (tid < 32){
            int v = s_wmin[lane];
#pragma unroll
            for (int d=16; d>0; d>>=1) v = min(v, __shfl_xor_sync(0xffffffffu, v, d));
            if (tid == 0){
                s_pick = v;
                float* r = out + (size_t)(b*POST_TOPN + it)*5;
                if (v < PRE_TOPN){
                    float x1=X1[v], y1=Y1[v], x2=X2[v], y2=Y2[v];
                    s_box[0]=x1; s_box[1]=y1; s_box[2]=x2; s_box[3]=y2; s_box[4]=AR[v];
                    r[0]=(float)b; r[1]=x1; r[2]=y1; r[3]=x2; r[4]=y2;
                    out[NB*POST_TOPN*5 + b*POST_TOPN + it] = SC[v];
                } else {
                    r[0]=0.f; r[1]=0.f; r[2]=0.f; r[3]=0.f; r[4]=0.f;
                    out[NB*POST_TOPN*5 + b*POST_TOPN + it] = 0.f;
                }
            }
        }
        __syncthreads();
        if (s_pick < PRE_TOPN && live){
            float bx1=s_box[0], by1=s_box[1], bx2=s_box[2], by2=s_box[3], ba=s_box[4];
#pragma unroll
            for (int j=0;j<6;j++){
                if (live & (1u<<j)){
                    float xx1 = fmaxf(bx1, mx1[j]);
                    float yy1 = fmaxf(by1, my1[j]);
                    float xx2 = fminf(bx2, mx2[j]);
                    float yy2 = fminf(by2, my2[j]);
                    float iw = fmaxf(xx2-xx1+1.f, 0.f);
                    float ih = fmaxf(yy2-yy1+1.f, 0.f);
                    float inter = iw*ih;
                    float iou = inter/(ba + mar[j] - inter);
                    if (iou > 0.7f) live &= ~(1u<<j);
                }
            }
        }
    }
}

// ---------------------------------------------------------------------------
extern "C" void kernel_launch(void* const* d_in, const int* in_sizes, int n_in,
                              void* d_out, int out_size) {
    (void)in_sizes; (void)n_in; (void)out_size;
    const float* base_feat = (const float*)d_in[0];
    const float* im_info   = (const float*)d_in[1];
    const float* conv_w    = (const float*)d_in[4];
    const float* conv_b    = (const float*)d_in[5];
    const float* cls_w     = (const float*)d_in[6];
    const float* cls_b     = (const float*)d_in[7];
    const float* bbox_w    = (const float*)d_in[8];
    const float* bbox_b    = (const float*)d_in[9];
    float* out = (float*)d_out;

    cudaFuncSetAttribute(head_kernel, cudaFuncAttributeMaxDynamicSharedMemorySize, 54*512*4);
    cudaFuncSetAttribute(sort_kernel, cudaFuncAttributeMaxDynamicSharedMemorySize, SORT_N*8);
    cudaFuncSetAttribute(nms_kernel,  cudaFuncAttributeMaxDynamicSharedMemorySize, PRE_TOPN*6*4);

    transpose_w_kernel<<<dim3(128,4), 256>>>(conv_w);
    init_kernel<<<(NB*NBUCKET + 255)/256, 256>>>();
    conv3x3_kernel<<<dim3(4,128,NSPLIT), 256>>>(base_feat);
    combine_kernel<<<(MTOT*CMID/4 + 255)/256, 256>>>(conv_b);
    head_kernel<<<148, 512, 54*512*4>>>(cls_w, cls_b, bbox_w, bbox_b, im_info);
    thresh_kernel<<<NB, 1024>>>();
    compact_kernel<<<(NB*NANCH + 255)/256, 256>>>();
    sort_kernel<<<NB, 1024, SORT_N*8>>>();
    nms_kernel<<<NB, 1024, PRE_TOPN*6*4>>>(out);
}